// round 1
// baseline (speedup 1.0000x reference)
#include <cuda_runtime.h>

#define NB 4
#define NV 4096
#define NT 8192
#define NP 4096
#define EPSF 1e-12f

#define TPB 128
#define TILE 256
#define CHUNKS 8
#define CHUNK_TRIS (NT / CHUNKS)

static __device__ float g_pos[NB * NV * 3];
static __device__ float4 g_tri[NB * NT * 4];
static __device__ unsigned int g_dmin[NB * NP];

__device__ __forceinline__ float safe_inv(float x) {
    return (fabsf(x) < EPSF) ? 1.0f : (1.0f / x);
}

// Kernel 1: sigmoid + layout transpose (B,3,4096)->(B,4096,3), and init dmin.
__global__ void prep_kernel(const float* __restrict__ vertices) {
    int idx = blockIdx.x * blockDim.x + threadIdx.x;
    if (idx < NB * 3 * NV) {
        int b = idx / (3 * NV);
        int r = idx - b * 3 * NV;
        int d = r / NV;
        int w = r - d * NV;
        float v = vertices[idx];
        float s = 1.0f / (1.0f + expf(-v));
        g_pos[(b * NV + w) * 3 + d] = s;
    }
    if (idx < NB * NP) g_dmin[idx] = 0x7F7FFFFFu;  // +FLT_MAX bits
}

// Kernel 2: per-triangle precompute (16 floats per triangle).
__global__ void tri_kernel(const int* __restrict__ faces) {
    int idx = blockIdx.x * blockDim.x + threadIdx.x;
    if (idx >= NB * NT) return;
    int b = idx >> 13;
    int t = idx & (NT - 1);
    int i0 = faces[t * 3 + 0], i1 = faces[t * 3 + 1], i2 = faces[t * 3 + 2];
    const float* base = g_pos + b * NV * 3;
    float ax = base[i0 * 3 + 0], ay = base[i0 * 3 + 1], az = base[i0 * 3 + 2];
    float bx = base[i1 * 3 + 0], by = base[i1 * 3 + 1], bz = base[i1 * 3 + 2];
    float cx = base[i2 * 3 + 0], cy = base[i2 * 3 + 1], cz = base[i2 * 3 + 2];
    float abx = bx - ax, aby = by - ay, abz = bz - az;
    float acx = cx - ax, acy = cy - ay, acz = cz - az;
    float bcx = cx - bx, bcy = cy - by, bcz = cz - bz;
    float ab2  = abx * abx + aby * aby + abz * abz;
    float ac2  = acx * acx + acy * acy + acz * acz;
    float abac = abx * acx + aby * acy + abz * acz;
    float bc2  = bcx * bcx + bcy * bcy + bcz * bcz;
    float den  = ab2 * ac2 - abac * abac;   // == va+vb+vc (per-pair constant)
    float4* o = g_tri + (size_t)idx * 4;
    o[0] = make_float4(ax, ay, az, ab2);
    o[1] = make_float4(abx, aby, abz, ac2);
    o[2] = make_float4(acx, acy, acz, abac);
    o[3] = make_float4(safe_inv(ab2), safe_inv(ac2), safe_inv(bc2), safe_inv(den));
}

struct Tri {
    float ax, ay, az;
    float abx, aby, abz;
    float acx, acy, acz;
    float ab2, ac2, abac, bc2;
    float iab2, iac2, ibc2, iden;
};

__device__ __forceinline__ float tri_sqdist(float px, float py, float pz, const Tri& T) {
    float apx = px - T.ax, apy = py - T.ay, apz = pz - T.az;
    float pa2 = apx * apx + apy * apy + apz * apz;
    float d1 = T.abx * apx + T.aby * apy + T.abz * apz;
    float d2 = T.acx * apx + T.acy * apy + T.acz * apz;
    float d3 = d1 - T.ab2;
    float d4 = d2 - T.abac;
    float d5 = d1 - T.abac;
    float d6 = d2 - T.ac2;
    float va = d3 * d6 - d5 * d4;
    float vb = d5 * d2 - d1 * d6;
    float vc = d1 * d4 - d3 * d2;
    float pb2 = fmaf(-2.0f, d1, pa2) + T.ab2;
    float pc2 = fmaf(-2.0f, d2, pa2) + T.ac2;
    float e = d4 - d3;
    float f = d5 - d6;
    // interior (default): |ap - v*ab - w*ac|^2, v=vb/den, w=vc/den (safe)
    float v = vb * T.iden;
    float w = vc * T.iden;
    float t1i = fmaf(w, T.abac, -d1);
    float t2i = fmaf(v, T.ab2, t1i + t1i);
    float t3i = fmaf(w, T.ac2, -(d2 + d2));
    float r = fmaf(w, t3i, fmaf(v, t2i, pa2));
    // edge BC: t = e/|bc|^2 (safe); dist = pb2 - 2 t e + t^2 |bc|^2
    float tb = e * T.ibc2;
    float ub = fmaf(tb, T.bc2, -(e + e));
    float cBC = fmaf(tb, ub, pb2);
    r = (va <= 0.0f && e >= 0.0f && f >= 0.0f) ? cBC : r;
    // edge AC
    float tc = d2 * T.iac2;
    float uc = fmaf(tc, T.ac2, -(d2 + d2));
    float cAC = fmaf(tc, uc, pa2);
    r = (vb <= 0.0f && d2 >= 0.0f && d6 <= 0.0f) ? cAC : r;
    // edge AB
    float ta = d1 * T.iab2;
    float ua = fmaf(ta, T.ab2, -(d1 + d1));
    float cAB = fmaf(ta, ua, pa2);
    r = (vc <= 0.0f && d1 >= 0.0f && d3 <= 0.0f) ? cAB : r;
    // vertex regions (highest priority last, matching reference where-order)
    r = (d6 >= 0.0f && d5 <= d6) ? pc2 : r;
    r = (d3 >= 0.0f && d4 <= d3) ? pb2 : r;
    r = (d1 <= 0.0f && d2 <= 0.0f) ? pa2 : r;
    return r;
}

// Kernel 3: main brute-force min over triangles. Each thread owns 2 points,
// iterates smem-staged triangle tiles, atomically mins into g_dmin.
__global__ void __launch_bounds__(TPB) dist_kernel(const float* __restrict__ pc) {
    __shared__ float4 sT[TILE * 4];
    int b = blockIdx.z;
    int tid = threadIdx.x;
    int i0 = blockIdx.y * (2 * TPB) + tid;
    int i1 = i0 + TPB;
    const float* P = pc + (size_t)b * NP * 3;
    float p0x = P[i0 * 3 + 0], p0y = P[i0 * 3 + 1], p0z = P[i0 * 3 + 2];
    float p1x = P[i1 * 3 + 0], p1y = P[i1 * 3 + 1], p1z = P[i1 * 3 + 2];
    float dm0 = 3.402823466e38f;
    float dm1 = 3.402823466e38f;
    const float4* triBase = g_tri + ((size_t)b * NT + (size_t)blockIdx.x * CHUNK_TRIS) * 4;

    for (int t0 = 0; t0 < CHUNK_TRIS * 4; t0 += TILE * 4) {
        __syncthreads();
#pragma unroll
        for (int i = 0; i < (TILE * 4) / TPB; i++)
            sT[tid + i * TPB] = triBase[t0 + tid + i * TPB];
        __syncthreads();
#pragma unroll 2
        for (int t = 0; t < TILE; t++) {
            float4 q0 = sT[t * 4 + 0];
            float4 q1 = sT[t * 4 + 1];
            float4 q2 = sT[t * 4 + 2];
            float4 q3 = sT[t * 4 + 3];
            Tri T;
            T.ax = q0.x;  T.ay = q0.y;  T.az = q0.z;  T.ab2 = q0.w;
            T.abx = q1.x; T.aby = q1.y; T.abz = q1.z; T.ac2 = q1.w;
            T.acx = q2.x; T.acy = q2.y; T.acz = q2.z; T.abac = q2.w;
            T.iab2 = q3.x; T.iac2 = q3.y; T.ibc2 = q3.z; T.iden = q3.w;
            T.bc2 = T.ab2 + T.ac2 - 2.0f * T.abac;
            dm0 = fminf(dm0, tri_sqdist(p0x, p0y, p0z, T));
            dm1 = fminf(dm1, tri_sqdist(p1x, p1y, p1z, T));
        }
    }
    atomicMin(&g_dmin[b * NP + i0], __float_as_uint(dm0));
    atomicMin(&g_dmin[b * NP + i1], __float_as_uint(dm1));
}

// Kernel 4: masked per-batch mean, then mean over batches.
__global__ void reduce_kernel(const float* __restrict__ pc, float* __restrict__ out) {
    __shared__ float sd[256];
    __shared__ float sm[256];
    int tid = threadIdx.x;
    float acc = 0.0f;
    for (int b = 0; b < NB; b++) {
        float ld = 0.0f, lm = 0.0f;
        for (int i = tid; i < NP; i += 256) {
            const float* p = pc + ((size_t)b * NP + i) * 3;
            float x = p[0], y = p[1], z = p[2];
            float m = (x != 0.0f || y != 0.0f || z != 0.0f) ? 1.0f : 0.0f;
            float d = __uint_as_float(g_dmin[b * NP + i]);
            ld += d * m;
            lm += m;
        }
        sd[tid] = ld;
        sm[tid] = lm;
        __syncthreads();
        for (int s = 128; s > 0; s >>= 1) {
            if (tid < s) {
                sd[tid] += sd[tid + s];
                sm[tid] += sm[tid + s];
            }
            __syncthreads();
        }
        if (tid == 0) acc += sd[0] / fmaxf(sm[0], 1.0f);
        __syncthreads();
    }
    if (tid == 0) out[0] = acc * (1.0f / NB);
}

extern "C" void kernel_launch(void* const* d_in, const int* in_sizes, int n_in,
                              void* d_out, int out_size) {
    const float* vertices = (const float*)d_in[0];
    const float* pc = (const float*)d_in[1];
    const int* faces = (const int*)d_in[2];
    float* out = (float*)d_out;

    prep_kernel<<<(NB * 3 * NV + 255) / 256, 256>>>(vertices);
    tri_kernel<<<(NB * NT + 255) / 256, 256>>>(faces);
    dist_kernel<<<dim3(CHUNKS, NP / (2 * TPB), NB), TPB>>>(pc);
    reduce_kernel<<<1, 256>>>(pc, out);
}

// round 2
// speedup vs baseline: 1.4752x; 1.4752x over previous
#include <cuda_runtime.h>

#define NB 4
#define NV 4096
#define NT 8192
#define NP 4096
#define EPSF 1e-12f

#define TPB 128
#define PPT 4              // points per thread
#define TILE 256           // triangles staged in smem per tile
#define CHUNKS 8
#define CHUNK_TRIS (NT / CHUNKS)

static __device__ float g_pos[NB * NV * 3];
static __device__ float4 g_tri[NB * NT * 4];
static __device__ unsigned int g_dmin[NB * NP];

__device__ __forceinline__ float safe_inv(float x) {
    return (fabsf(x) < EPSF) ? 1.0f : (1.0f / x);
}

// Kernel 1: sigmoid + layout transpose (B,3,4096)->(B,4096,3), and init dmin.
__global__ void prep_kernel(const float* __restrict__ vertices) {
    int idx = blockIdx.x * blockDim.x + threadIdx.x;
    if (idx < NB * 3 * NV) {
        int b = idx / (3 * NV);
        int r = idx - b * 3 * NV;
        int d = r / NV;
        int w = r - d * NV;
        float v = vertices[idx];
        float s = 1.0f / (1.0f + expf(-v));
        g_pos[(b * NV + w) * 3 + d] = s;
    }
    if (idx < NB * NP) g_dmin[idx] = 0x7F7FFFFFu;  // +FLT_MAX bits
}

// Kernel 2: per-triangle precompute. 16 floats per triangle:
//   q0 = (ax, ay, az, ab2)
//   q1 = (abx, aby, abz, ac2)
//   q2 = (acx, acy, acz, abac)
//   q3 = (iab2, iac2, ibc2, iden)
__global__ void tri_kernel(const int* __restrict__ faces) {
    int idx = blockIdx.x * blockDim.x + threadIdx.x;
    if (idx >= NB * NT) return;
    int b = idx >> 13;
    int t = idx & (NT - 1);
    int i0 = faces[t * 3 + 0], i1 = faces[t * 3 + 1], i2 = faces[t * 3 + 2];
    const float* base = g_pos + b * NV * 3;
    float ax = base[i0 * 3 + 0], ay = base[i0 * 3 + 1], az = base[i0 * 3 + 2];
    float bx = base[i1 * 3 + 0], by = base[i1 * 3 + 1], bz = base[i1 * 3 + 2];
    float cx = base[i2 * 3 + 0], cy = base[i2 * 3 + 1], cz = base[i2 * 3 + 2];
    float abx = bx - ax, aby = by - ay, abz = bz - az;
    float acx = cx - ax, acy = cy - ay, acz = cz - az;
    float bcx = cx - bx, bcy = cy - by, bcz = cz - bz;
    float ab2  = abx * abx + aby * aby + abz * abz;
    float ac2  = acx * acx + acy * acy + acz * acz;
    float abac = abx * acx + aby * acy + abz * acz;
    float bc2  = bcx * bcx + bcy * bcy + bcz * bcz;
    float den  = ab2 * ac2 - abac * abac;   // == va+vb+vc (per-triangle constant)
    float4* o = g_tri + (size_t)idx * 4;
    o[0] = make_float4(ax, ay, az, ab2);
    o[1] = make_float4(abx, aby, abz, ac2);
    o[2] = make_float4(acx, acy, acz, abac);
    o[3] = make_float4(safe_inv(ab2), safe_inv(ac2), safe_inv(bc2), safe_inv(den));
}

// Min-of-clamped-segments closest-distance. Equivalent to the Ericson region
// chain (incl. degenerate duplicate-vertex faces): boundary distance is the min
// over the three clamped segments; interior distance applies iff the point's
// barycentric projection is strictly inside (va,vb,vc > 0; degenerate faces
// have va+vb+vc == 0 so the interior branch is auto-excluded).
__device__ __forceinline__ float tri_min_sqdist(
    float px, float py, float pz,
    float ax, float ay, float az,
    float abx, float aby, float abz,
    float acx, float acy, float acz,
    float ab2, float ac2, float abac, float bc2, float abac2,
    float iab2, float iac2, float ibc2, float iden)
{
    float apx = px - ax, apy = py - ay, apz = pz - az;
    float pa2 = fmaf(apx, apx, fmaf(apy, apy, apz * apz));
    float d1  = fmaf(abx, apx, fmaf(aby, apy, abz * apz));
    float d2  = fmaf(acx, apx, fmaf(acy, apy, acz * apz));
    float td1 = d1 + d1, td2 = d2 + d2;
    // segment AB: t = clamp(d1/|ab|^2); dist = pa2 - 2 t d1 + t^2 |ab|^2
    float tab = __saturatef(d1 * iab2);
    float dAB = fmaf(tab, fmaf(tab, ab2, -td1), pa2);
    // segment AC
    float tac = __saturatef(d2 * iac2);
    float dAC = fmaf(tac, fmaf(tac, ac2, -td2), pa2);
    // segment BC: t = clamp(e/|bc|^2), e = (d4-d3); dist from B
    float d3 = d1 - ab2, d4 = d2 - abac, d5 = d1 - abac, d6 = d2 - ac2;
    float e   = d4 - d3;
    float pb2 = (pa2 - td1) + ab2;
    float tbc = __saturatef(e * ibc2);
    float dBC = fmaf(tbc, fmaf(tbc, bc2, -(e + e)), pb2);
    // interior
    float va = fmaf(d3, d6, -(d5 * d4));
    float vb = fmaf(d5, d2, -(d1 * d6));
    float vc = fmaf(d1, d4, -(d3 * d2));
    float v = vb * iden, w = vc * iden;
    float u1 = fmaf(w, abac2, -td1);
    float u2 = fmaf(v, ab2, u1);
    float u3 = fmaf(w, ac2, -td2);
    float dI = fmaf(w, u3, fmaf(v, u2, pa2));
    bool inside = fminf(va, fminf(vb, vc)) > 0.0f;
    float m = fminf(dAB, dAC);
    m = fminf(m, dBC);
    m = inside ? fminf(m, dI) : m;
    return m;
}

// Kernel 3: brute-force min over triangles. Each thread owns PPT points,
// iterates smem-staged triangle tiles, atomically mins into g_dmin.
__global__ void __launch_bounds__(TPB) dist_kernel(const float* __restrict__ pc) {
    __shared__ float4 sT[TILE * 4];
    int b = blockIdx.z;
    int tid = threadIdx.x;
    const float* P = pc + (size_t)b * NP * 3;
    int ibase = blockIdx.y * (PPT * TPB) + tid;

    float px[PPT], py[PPT], pz[PPT], dm[PPT];
#pragma unroll
    for (int k = 0; k < PPT; k++) {
        int i = ibase + k * TPB;
        px[k] = P[i * 3 + 0];
        py[k] = P[i * 3 + 1];
        pz[k] = P[i * 3 + 2];
        dm[k] = 3.402823466e38f;
    }

    const float4* triBase = g_tri + ((size_t)b * NT + (size_t)blockIdx.x * CHUNK_TRIS) * 4;

    for (int t0 = 0; t0 < CHUNK_TRIS * 4; t0 += TILE * 4) {
        __syncthreads();
#pragma unroll
        for (int i = 0; i < (TILE * 4) / TPB; i++)
            sT[tid + i * TPB] = triBase[t0 + tid + i * TPB];
        __syncthreads();
#pragma unroll 2
        for (int t = 0; t < TILE; t++) {
            float4 q0 = sT[t * 4 + 0];
            float4 q1 = sT[t * 4 + 1];
            float4 q2 = sT[t * 4 + 2];
            float4 q3 = sT[t * 4 + 3];
            float ab2 = q0.w, ac2 = q1.w, abac = q2.w;
            float abac2 = abac + abac;
            float bc2 = (ab2 + ac2) - abac2;
#pragma unroll
            for (int k = 0; k < PPT; k++) {
                dm[k] = fminf(dm[k], tri_min_sqdist(
                    px[k], py[k], pz[k],
                    q0.x, q0.y, q0.z,
                    q1.x, q1.y, q1.z,
                    q2.x, q2.y, q2.z,
                    ab2, ac2, abac, bc2, abac2,
                    q3.x, q3.y, q3.z, q3.w));
            }
        }
    }
#pragma unroll
    for (int k = 0; k < PPT; k++)
        atomicMin(&g_dmin[b * NP + ibase + k * TPB], __float_as_uint(dm[k]));
}

// Kernel 4: masked per-batch mean then mean over batches.
// 1024 threads = 4 groups of 256, group g handles batch g in parallel.
__global__ void reduce_kernel(const float* __restrict__ pc, float* __restrict__ out) {
    __shared__ float sd[1024];
    __shared__ float sm[1024];
    int tid = threadIdx.x;
    int b = tid >> 8;
    int lane = tid & 255;
    float ld = 0.0f, lm = 0.0f;
    for (int i = lane; i < NP; i += 256) {
        const float* p = pc + ((size_t)b * NP + i) * 3;
        float x = p[0], y = p[1], z = p[2];
        float m = (x != 0.0f || y != 0.0f || z != 0.0f) ? 1.0f : 0.0f;
        ld += __uint_as_float(g_dmin[b * NP + i]) * m;
        lm += m;
    }
    sd[tid] = ld;
    sm[tid] = lm;
    __syncthreads();
    for (int s = 128; s > 0; s >>= 1) {
        if (lane < s) {
            sd[tid] += sd[tid + s];
            sm[tid] += sm[tid + s];
        }
        __syncthreads();
    }
    if (tid == 0) {
        float acc = 0.0f;
        for (int bb = 0; bb < NB; bb++)
            acc += sd[bb * 256] / fmaxf(sm[bb * 256], 1.0f);
        out[0] = acc * (1.0f / NB);
    }
}

extern "C" void kernel_launch(void* const* d_in, const int* in_sizes, int n_in,
                              void* d_out, int out_size) {
    const float* vertices = (const float*)d_in[0];
    const float* pc = (const float*)d_in[1];
    const int* faces = (const int*)d_in[2];
    float* out = (float*)d_out;

    prep_kernel<<<(NB * 3 * NV + 255) / 256, 256>>>(vertices);
    tri_kernel<<<(NB * NT + 255) / 256, 256>>>(faces);
    dist_kernel<<<dim3(CHUNKS, NP / (PPT * TPB), NB), TPB>>>(pc);
    reduce_kernel<<<1, 1024>>>(pc, out);
}

// round 3
// speedup vs baseline: 1.7496x; 1.1860x over previous
#include <cuda_runtime.h>

#define NB 4
#define NV 4096
#define NT 8192
#define NP 4096
#define EPSF 1e-12f

#define TPB 128
#define PPT 4              // points per thread (2 packed f32x2 streams)
#define TILE 128           // triangles staged in smem per tile
#define CHUNKS 32
#define CHUNK_TRIS (NT / CHUNKS)
#define F4_PER_TRI 11      // 176 bytes per triangle, constants pre-duplicated

typedef unsigned long long ull;

static __device__ float g_pos[NB * NV * 3];
static __device__ float4 g_tri2[NB * NT * F4_PER_TRI];
static __device__ unsigned int g_dmin[NB * NP];
static __device__ float g_psum[32];
static __device__ float g_pcnt[32];

// ---------- packed f32x2 helpers (SASS FADD2/FMUL2/FFMA2) ----------
__device__ __forceinline__ ull f2x(float lo, float hi) {
    ull r; asm("mov.b64 %0, {%1, %2};" : "=l"(r) : "f"(lo), "f"(hi)); return r;
}
__device__ __forceinline__ void f2x_un(ull a, float& lo, float& hi) {
    asm("mov.b64 {%0, %1}, %2;" : "=f"(lo), "=f"(hi) : "l"(a));
}
__device__ __forceinline__ ull f2x_add(ull a, ull b) {
    ull r; asm("add.rn.f32x2 %0, %1, %2;" : "=l"(r) : "l"(a), "l"(b)); return r;
}
__device__ __forceinline__ ull f2x_mul(ull a, ull b) {
    ull r; asm("mul.rn.f32x2 %0, %1, %2;" : "=l"(r) : "l"(a), "l"(b)); return r;
}
__device__ __forceinline__ ull f2x_fma(ull a, ull b, ull c) {
    ull r; asm("fma.rn.f32x2 %0, %1, %2, %3;" : "=l"(r) : "l"(a), "l"(b), "l"(c)); return r;
}

__device__ __forceinline__ float safe_inv(float x) {
    return (fabsf(x) < EPSF) ? 1.0f : (1.0f / x);
}
__device__ __forceinline__ float clamp01(float x) {
    return fminf(fmaxf(x, 0.0f), 1.0f);
}

// Kernel 1: sigmoid + layout transpose (B,3,4096)->(B,4096,3), and init dmin.
__global__ void prep_kernel(const float* __restrict__ vertices) {
    int idx = blockIdx.x * blockDim.x + threadIdx.x;
    if (idx < NB * 3 * NV) {
        int b = idx / (3 * NV);
        int r = idx - b * 3 * NV;
        int d = r / NV;
        int w = r - d * NV;
        float v = vertices[idx];
        float s = 1.0f / (1.0f + expf(-v));
        g_pos[(b * NV + w) * 3 + d] = s;
    }
    if (idx < NB * NP) g_dmin[idx] = 0x7F7FFFFFu;  // +FLT_MAX bits
}

// Kernel 2: per-triangle precompute, constants duplicated into f32x2 pairs.
// Slot map (each float4 holds two duplicated constants {c0,c0,c1,c1}):
//  0:(-ax,-ay) 1:(-az,abx) 2:(aby,abz) 3:(acx,acy) 4:(acz,ab2)
//  5:(ac2,bc2) 6:(2abac,-ab2) 7:(-abac,-ac2) 8:(iab2,iac2) 9:(ibc2,iden) 10:(den,0)
__global__ void tri_kernel(const int* __restrict__ faces) {
    int idx = blockIdx.x * blockDim.x + threadIdx.x;
    if (idx >= NB * NT) return;
    int b = idx >> 13;
    int t = idx & (NT - 1);
    int i0 = faces[t * 3 + 0], i1 = faces[t * 3 + 1], i2 = faces[t * 3 + 2];
    const float* base = g_pos + b * NV * 3;
    float ax = base[i0 * 3 + 0], ay = base[i0 * 3 + 1], az = base[i0 * 3 + 2];
    float bx = base[i1 * 3 + 0], by = base[i1 * 3 + 1], bz = base[i1 * 3 + 2];
    float cx = base[i2 * 3 + 0], cy = base[i2 * 3 + 1], cz = base[i2 * 3 + 2];
    float abx = bx - ax, aby = by - ay, abz = bz - az;
    float acx = cx - ax, acy = cy - ay, acz = cz - az;
    float bcx = cx - bx, bcy = cy - by, bcz = cz - bz;
    float ab2  = abx * abx + aby * aby + abz * abz;
    float ac2  = acx * acx + acy * acy + acz * acz;
    float abac = abx * acx + aby * acy + abz * acz;
    float bc2  = bcx * bcx + bcy * bcy + bcz * bcz;
    float den  = ab2 * ac2 - abac * abac;   // == va+vb+vc
    float4* o = g_tri2 + (size_t)idx * F4_PER_TRI;
    o[0]  = make_float4(-ax, -ax, -ay, -ay);
    o[1]  = make_float4(-az, -az, abx, abx);
    o[2]  = make_float4(aby, aby, abz, abz);
    o[3]  = make_float4(acx, acx, acy, acy);
    o[4]  = make_float4(acz, acz, ab2, ab2);
    o[5]  = make_float4(ac2, ac2, bc2, bc2);
    o[6]  = make_float4(abac + abac, abac + abac, -ab2, -ab2);
    o[7]  = make_float4(-abac, -abac, -ac2, -ac2);
    o[8]  = make_float4(safe_inv(ab2), safe_inv(ab2), safe_inv(ac2), safe_inv(ac2));
    o[9]  = make_float4(safe_inv(bc2), safe_inv(bc2), safe_inv(den), safe_inv(den));
    o[10] = make_float4(den, den, 0.0f, 0.0f);
}

// Packed min-sqdist: one triangle vs two points (lo/hi lanes of f32x2).
// min over 3 clamped segments, plus interior iff barycentrics all > 0.
__device__ __forceinline__ float2 tri_pair(const ulonglong2* __restrict__ tp,
                                           ull px, ull py, ull pz,
                                           ull M2, ull NEG1)
{
    ulonglong2 c0 = tp[0], c1 = tp[1], c2 = tp[2], c3 = tp[3], c4 = tp[4];
    ull apx = f2x_add(px, c0.x);
    ull apy = f2x_add(py, c0.y);
    ull apz = f2x_add(pz, c1.x);
    ull pa2 = f2x_mul(apz, apz); pa2 = f2x_fma(apy, apy, pa2); pa2 = f2x_fma(apx, apx, pa2);
    ull d1  = f2x_mul(c2.y, apz); d1 = f2x_fma(c2.x, apy, d1); d1 = f2x_fma(c1.y, apx, d1);
    ull d2  = f2x_mul(c4.x, apz); d2 = f2x_fma(c3.y, apy, d2); d2 = f2x_fma(c3.x, apx, d2);
    ulonglong2 c5 = tp[5], c6 = tp[6], c7 = tp[7], c8 = tp[8], c9 = tp[9];
    ull ab2 = c4.y, ac2 = c5.x, bc2 = c5.y;
    ull ntd1 = f2x_mul(d1, M2);
    ull ntd2 = f2x_mul(d2, M2);
    float s0, s1;
    // segment AB
    f2x_un(f2x_mul(d1, c8.x), s0, s1);
    ull tab = f2x(clamp01(s0), clamp01(s1));
    ull dAB = f2x_fma(tab, f2x_fma(tab, ab2, ntd1), pa2);
    // segment AC
    f2x_un(f2x_mul(d2, c8.y), s0, s1);
    ull tac = f2x(clamp01(s0), clamp01(s1));
    ull dAC = f2x_fma(tac, f2x_fma(tac, ac2, ntd2), pa2);
    // segment BC
    ull d3 = f2x_add(d1, c6.y);
    ull d4 = f2x_add(d2, c7.x);
    ull d5 = f2x_add(d1, c7.x);
    ull d6 = f2x_add(d2, c7.y);
    ull e  = f2x_fma(d3, NEG1, d4);
    ull pb2 = f2x_add(f2x_add(pa2, ntd1), ab2);
    f2x_un(f2x_mul(e, c9.x), s0, s1);
    ull tbc = f2x(clamp01(s0), clamp01(s1));
    ull ne2 = f2x_mul(e, M2);
    ull dBC = f2x_fma(tbc, f2x_fma(tbc, bc2, ne2), pb2);
    // interior
    ull vb = f2x_fma(f2x_mul(d1, d6), NEG1, f2x_mul(d5, d2));
    ull vc = f2x_fma(f2x_mul(d3, d2), NEG1, f2x_mul(d1, d4));
    ull va = f2x_fma(vc, NEG1, f2x_fma(vb, NEG1, tp[10].x));
    ull iden = c9.y;
    ull v = f2x_mul(vb, iden);
    ull w = f2x_mul(vc, iden);
    ull u2 = f2x_fma(v, ab2, f2x_fma(w, c6.x, ntd1));
    ull u3 = f2x_fma(w, ac2, ntd2);
    ull dI = f2x_fma(w, u3, f2x_fma(v, u2, pa2));
    // scalar tail (alu pipe)
    float ab0, ab1, ac0, ac1, bc0, bc1, va0, va1, vb0, vb1, vc0, vc1, di0, di1;
    f2x_un(dAB, ab0, ab1);
    f2x_un(dAC, ac0, ac1);
    f2x_un(dBC, bc0, bc1);
    f2x_un(va, va0, va1);
    f2x_un(vb, vb0, vb1);
    f2x_un(vc, vc0, vc1);
    f2x_un(dI, di0, di1);
    float m0 = fminf(fminf(ab0, ac0), bc0);
    float m1 = fminf(fminf(ab1, ac1), bc1);
    float i0 = fminf(va0, fminf(vb0, vc0));
    float i1 = fminf(va1, fminf(vb1, vc1));
    if (i0 > 0.0f) m0 = fminf(m0, di0);
    if (i1 > 0.0f) m1 = fminf(m1, di1);
    return make_float2(m0, m1);
}

// Kernel 3: brute-force min over triangles, packed f32x2, smem-staged tris.
__global__ void __launch_bounds__(TPB) dist_kernel(const float* __restrict__ pc) {
    __shared__ float4 sT[TILE * F4_PER_TRI];
    int b = blockIdx.z;
    int tid = threadIdx.x;
    const float* P = pc + (size_t)b * NP * 3;
    int ibase = blockIdx.y * (PPT * TPB) + tid;

    float px[PPT], py[PPT], pz[PPT], dm[PPT];
#pragma unroll
    for (int k = 0; k < PPT; k++) {
        int i = ibase + k * TPB;
        px[k] = P[i * 3 + 0];
        py[k] = P[i * 3 + 1];
        pz[k] = P[i * 3 + 2];
        dm[k] = 3.402823466e38f;
    }
    ull px2[2], py2[2], pz2[2];
#pragma unroll
    for (int j = 0; j < 2; j++) {
        px2[j] = f2x(px[2 * j], px[2 * j + 1]);
        py2[j] = f2x(py[2 * j], py[2 * j + 1]);
        pz2[j] = f2x(pz[2 * j], pz[2 * j + 1]);
    }
    const ull M2 = f2x(-2.0f, -2.0f);
    const ull NEG1 = f2x(-1.0f, -1.0f);

    const float4* triBase = g_tri2 + ((size_t)b * NT + (size_t)blockIdx.x * CHUNK_TRIS) * F4_PER_TRI;

    for (int tt = 0; tt < CHUNK_TRIS / TILE; tt++) {
        __syncthreads();
        const float4* src = triBase + (size_t)tt * TILE * F4_PER_TRI;
#pragma unroll
        for (int i = 0; i < F4_PER_TRI; i++)
            sT[tid + i * TPB] = src[tid + i * TPB];
        __syncthreads();
        for (int t = 0; t < TILE; t++) {
            const ulonglong2* tp = reinterpret_cast<const ulonglong2*>(sT + t * F4_PER_TRI);
            float2 r0 = tri_pair(tp, px2[0], py2[0], pz2[0], M2, NEG1);
            float2 r1 = tri_pair(tp, px2[1], py2[1], pz2[1], M2, NEG1);
            dm[0] = fminf(dm[0], r0.x);
            dm[1] = fminf(dm[1], r0.y);
            dm[2] = fminf(dm[2], r1.x);
            dm[3] = fminf(dm[3], r1.y);
        }
    }
#pragma unroll
    for (int k = 0; k < PPT; k++)
        atomicMin(&g_dmin[b * NP + ibase + k * TPB], __float_as_uint(dm[k]));
}

// Kernel 4a: parallel partial reduce. 32 blocks (8 slices x 4 batches) x 512 thr.
__global__ void reduceA_kernel(const float* __restrict__ pc) {
    __shared__ float sd[512];
    __shared__ float sc[512];
    int tid = threadIdx.x;
    int blk = blockIdx.x;
    int b = blk >> 3;
    int slice = blk & 7;
    int i = slice * 512 + tid;
    const float* p = pc + ((size_t)b * NP + i) * 3;
    float x = p[0], y = p[1], z = p[2];
    float m = (x != 0.0f || y != 0.0f || z != 0.0f) ? 1.0f : 0.0f;
    sd[tid] = __uint_as_float(g_dmin[b * NP + i]) * m;
    sc[tid] = m;
    __syncthreads();
    for (int s = 256; s > 0; s >>= 1) {
        if (tid < s) {
            sd[tid] += sd[tid + s];
            sc[tid] += sc[tid + s];
        }
        __syncthreads();
    }
    if (tid == 0) {
        g_psum[blk] = sd[0];
        g_pcnt[blk] = sc[0];
    }
}

// Kernel 4b: deterministic fixed-order final combine.
__global__ void reduceB_kernel(float* __restrict__ out) {
    if (threadIdx.x == 0) {
        float acc = 0.0f;
        for (int b = 0; b < NB; b++) {
            float s = 0.0f, c = 0.0f;
#pragma unroll
            for (int j = 0; j < 8; j++) {
                s += g_psum[b * 8 + j];
                c += g_pcnt[b * 8 + j];
            }
            acc += s / fmaxf(c, 1.0f);
        }
        out[0] = acc * (1.0f / NB);
    }
}

extern "C" void kernel_launch(void* const* d_in, const int* in_sizes, int n_in,
                              void* d_out, int out_size) {
    const float* vertices = (const float*)d_in[0];
    const float* pc = (const float*)d_in[1];
    const int* faces = (const int*)d_in[2];
    float* out = (float*)d_out;

    prep_kernel<<<(NB * 3 * NV + 255) / 256, 256>>>(vertices);
    tri_kernel<<<(NB * NT + 255) / 256, 256>>>(faces);
    dist_kernel<<<dim3(CHUNKS, NP / (PPT * TPB), NB), TPB>>>(pc);
    reduceA_kernel<<<32, 512>>>(pc);
    reduceB_kernel<<<1, 32>>>(out);
}

// round 4
// speedup vs baseline: 1.8078x; 1.0333x over previous
#include <cuda_runtime.h>

#define NB 4
#define NV 4096
#define NT 8192
#define NP 4096
#define EPSF 1e-12f

#define TPB 128
#define PPT 4              // points per thread (2 packed f32x2 streams)
#define TILE 128           // triangles staged in smem per tile
#define CHUNKS 32
#define CHUNK_TRIS (NT / CHUNKS)
#define F4_PER_TRI 9       // 144 bytes per triangle, constants pre-duplicated

typedef unsigned long long ull;

static __device__ float g_pos[NB * NV * 3];
static __device__ float4 g_tri2[NB * NT * F4_PER_TRI];
static __device__ unsigned int g_dmin[NB * NP];
static __device__ float g_psum[32];
static __device__ float g_pcnt[32];

// ---------- packed f32x2 helpers (SASS FADD2/FMUL2/FFMA2) ----------
__device__ __forceinline__ ull f2x(float lo, float hi) {
    ull r; asm("mov.b64 %0, {%1, %2};" : "=l"(r) : "f"(lo), "f"(hi)); return r;
}
__device__ __forceinline__ void f2x_un(ull a, float& lo, float& hi) {
    asm("mov.b64 {%0, %1}, %2;" : "=f"(lo), "=f"(hi) : "l"(a));
}
__device__ __forceinline__ ull f2x_add(ull a, ull b) {
    ull r; asm("add.rn.f32x2 %0, %1, %2;" : "=l"(r) : "l"(a), "l"(b)); return r;
}
__device__ __forceinline__ ull f2x_mul(ull a, ull b) {
    ull r; asm("mul.rn.f32x2 %0, %1, %2;" : "=l"(r) : "l"(a), "l"(b)); return r;
}
__device__ __forceinline__ ull f2x_fma(ull a, ull b, ull c) {
    ull r; asm("fma.rn.f32x2 %0, %1, %2, %3;" : "=l"(r) : "l"(a), "l"(b), "l"(c)); return r;
}

__device__ __forceinline__ float safe_inv(float x) {
    return (fabsf(x) < EPSF) ? 1.0f : (1.0f / x);
}

// Kernel 1: sigmoid + layout transpose (B,3,4096)->(B,4096,3), and init dmin.
__global__ void prep_kernel(const float* __restrict__ vertices) {
    int idx = blockIdx.x * blockDim.x + threadIdx.x;
    if (idx < NB * 3 * NV) {
        int b = idx / (3 * NV);
        int r = idx - b * 3 * NV;
        int d = r / NV;
        int w = r - d * NV;
        float v = vertices[idx];
        float s = 1.0f / (1.0f + expf(-v));
        g_pos[(b * NV + w) * 3 + d] = s;
    }
    if (idx < NB * NP) g_dmin[idx] = 0x7F7FFFFFu;  // +FLT_MAX bits
}

// Kernel 2: per-triangle precompute, constants duplicated into f32x2 pairs.
// Pair map: c0:(-ax,-ay) c1:(-az,abx) c2:(aby,abz) c3:(acx,acy) c4:(acz,-ab2)
//           c5:(-abac,-ac2) c6:(-iab2,-iac2) c7:(-ibc2,den) c8:(-iden,0)
__global__ void tri_kernel(const int* __restrict__ faces) {
    int idx = blockIdx.x * blockDim.x + threadIdx.x;
    if (idx >= NB * NT) return;
    int b = idx >> 13;
    int t = idx & (NT - 1);
    int i0 = faces[t * 3 + 0], i1 = faces[t * 3 + 1], i2 = faces[t * 3 + 2];
    const float* base = g_pos + b * NV * 3;
    float ax = base[i0 * 3 + 0], ay = base[i0 * 3 + 1], az = base[i0 * 3 + 2];
    float bx = base[i1 * 3 + 0], by = base[i1 * 3 + 1], bz = base[i1 * 3 + 2];
    float cx = base[i2 * 3 + 0], cy = base[i2 * 3 + 1], cz = base[i2 * 3 + 2];
    float abx = bx - ax, aby = by - ay, abz = bz - az;
    float acx = cx - ax, acy = cy - ay, acz = cz - az;
    float bcx = cx - bx, bcy = cy - by, bcz = cz - bz;
    float ab2  = abx * abx + aby * aby + abz * abz;
    float ac2  = acx * acx + acy * acy + acz * acz;
    float abac = abx * acx + aby * acy + abz * acz;
    float bc2  = bcx * bcx + bcy * bcy + bcz * bcz;
    float den  = ab2 * ac2 - abac * abac;   // == va+vb+vc
    float4* o = g_tri2 + (size_t)idx * F4_PER_TRI;
    o[0] = make_float4(-ax, -ax, -ay, -ay);
    o[1] = make_float4(-az, -az, abx, abx);
    o[2] = make_float4(aby, aby, abz, abz);
    o[3] = make_float4(acx, acx, acy, acy);
    o[4] = make_float4(acz, acz, -ab2, -ab2);
    o[5] = make_float4(-abac, -abac, -ac2, -ac2);
    o[6] = make_float4(-safe_inv(ab2), -safe_inv(ab2), -safe_inv(ac2), -safe_inv(ac2));
    o[7] = make_float4(-safe_inv(bc2), -safe_inv(bc2), den, den);
    o[8] = make_float4(-safe_inv(den), -safe_inv(den), 0.0f, 0.0f);
}

// Min-of-features closest distance, one triangle vs two packed points.
// m = min(pa2, pb2, pc2,
//         lineAB if 0<d1<ab2, lineAC if 0<d2<ac2 (d6<0), lineBC if e>0 && f>0,
//         face   if va,vb,vc > 0)
// Line dists: pa2 - d1^2/ab2 etc. Face: pa2 - (vb*d1 + vc*d2)/den (normal eqs).
__device__ __forceinline__ float2 tri_pair(const ulonglong2* __restrict__ tp,
                                           ull px, ull py, ull pz, ull NEG1)
{
    ulonglong2 c0 = tp[0], c1 = tp[1], c2 = tp[2], c3 = tp[3], c4 = tp[4];
    ull apx = f2x_add(px, c0.x);
    ull apy = f2x_add(py, c0.y);
    ull apz = f2x_add(pz, c1.x);
    ull pa2 = f2x_fma(apx, apx, f2x_fma(apy, apy, f2x_mul(apz, apz)));
    ull d1  = f2x_fma(c1.y, apx, f2x_fma(c2.x, apy, f2x_mul(c2.y, apz)));
    ull d2  = f2x_fma(c3.x, apx, f2x_fma(c3.y, apy, f2x_mul(c4.x, apz)));
    ulonglong2 c5 = tp[5], c6 = tp[6], c7 = tp[7], c8 = tp[8];
    ull d3 = f2x_add(d1, c4.y);            // d1 - ab2
    ull d4 = f2x_add(d2, c5.x);            // d2 - abac
    ull d5 = f2x_add(d1, c5.x);            // d1 - abac
    ull d6 = f2x_add(d2, c5.y);            // d2 - ac2
    ull pb2 = f2x_fma(f2x_add(d1, d3), NEG1, pa2);
    ull pc2 = f2x_fma(f2x_add(d2, d6), NEG1, pa2);
    ull e = f2x_fma(d3, NEG1, d4);
    ull f = f2x_fma(d6, NEG1, d5);
    ull vAB = f2x_fma(f2x_mul(d1, d1), c6.x, pa2);
    ull vAC = f2x_fma(f2x_mul(d2, d2), c6.y, pa2);
    ull vBC = f2x_fma(f2x_mul(e, e), c7.x, pb2);
    ull vb = f2x_fma(f2x_mul(d1, d6), NEG1, f2x_mul(d5, d2));
    ull vc = f2x_fma(f2x_mul(d3, d2), NEG1, f2x_mul(d1, d4));
    ull va = f2x_fma(f2x_add(vb, vc), NEG1, c7.y);
    ull dI = f2x_fma(f2x_fma(vc, d2, f2x_mul(vb, d1)), c8.x, pa2);

    float pa0, pa1, pb0, pb1, pcl0, pcl1;
    float D10, D11, D30, D31, D20, D21, D60, D61, E0, E1, F0, F1;
    float AB0, AB1, AC0, AC1, BC0, BC1;
    float VA0, VA1, VB0, VB1, VC0, VC1, DI0, DI1;
    f2x_un(pa2, pa0, pa1);
    f2x_un(pb2, pb0, pb1);
    f2x_un(pc2, pcl0, pcl1);
    f2x_un(d1, D10, D11);
    f2x_un(d3, D30, D31);
    f2x_un(d2, D20, D21);
    f2x_un(d6, D60, D61);
    f2x_un(e, E0, E1);
    f2x_un(f, F0, F1);
    f2x_un(vAB, AB0, AB1);
    f2x_un(vAC, AC0, AC1);
    f2x_un(vBC, BC0, BC1);
    f2x_un(va, VA0, VA1);
    f2x_un(vb, VB0, VB1);
    f2x_un(vc, VC0, VC1);
    f2x_un(dI, DI0, DI1);

    float m0 = fminf(pa0, fminf(pb0, pcl0));
    float m1 = fminf(pa1, fminf(pb1, pcl1));
    if (D10 > 0.0f && D30 < 0.0f) m0 = fminf(m0, AB0);
    if (D11 > 0.0f && D31 < 0.0f) m1 = fminf(m1, AB1);
    if (D20 > 0.0f && D60 < 0.0f) m0 = fminf(m0, AC0);
    if (D21 > 0.0f && D61 < 0.0f) m1 = fminf(m1, AC1);
    if (E0 > 0.0f && F0 > 0.0f) m0 = fminf(m0, BC0);
    if (E1 > 0.0f && F1 > 0.0f) m1 = fminf(m1, BC1);
    if (fminf(VA0, fminf(VB0, VC0)) > 0.0f) m0 = fminf(m0, DI0);
    if (fminf(VA1, fminf(VB1, VC1)) > 0.0f) m1 = fminf(m1, DI1);
    return make_float2(m0, m1);
}

// Kernel 3: brute-force min over triangles, packed f32x2, smem-staged tris.
__global__ void __launch_bounds__(TPB) dist_kernel(const float* __restrict__ pc) {
    __shared__ float4 sT[TILE * F4_PER_TRI];
    int b = blockIdx.z;
    int tid = threadIdx.x;
    const float* P = pc + (size_t)b * NP * 3;
    int ibase = blockIdx.y * (PPT * TPB) + tid;

    float px[PPT], py[PPT], pz[PPT], dm[PPT];
#pragma unroll
    for (int k = 0; k < PPT; k++) {
        int i = ibase + k * TPB;
        px[k] = P[i * 3 + 0];
        py[k] = P[i * 3 + 1];
        pz[k] = P[i * 3 + 2];
        dm[k] = 3.402823466e38f;
    }
    ull px2[2], py2[2], pz2[2];
#pragma unroll
    for (int j = 0; j < 2; j++) {
        px2[j] = f2x(px[2 * j], px[2 * j + 1]);
        py2[j] = f2x(py[2 * j], py[2 * j + 1]);
        pz2[j] = f2x(pz[2 * j], pz[2 * j + 1]);
    }
    const ull NEG1 = f2x(-1.0f, -1.0f);

    const float4* triBase = g_tri2 + ((size_t)b * NT + (size_t)blockIdx.x * CHUNK_TRIS) * F4_PER_TRI;

    for (int tt = 0; tt < CHUNK_TRIS / TILE; tt++) {
        __syncthreads();
        const float4* src = triBase + (size_t)tt * TILE * F4_PER_TRI;
#pragma unroll
        for (int i = 0; i < F4_PER_TRI; i++)
            sT[tid + i * TPB] = src[tid + i * TPB];
        __syncthreads();
#pragma unroll 2
        for (int t = 0; t < TILE; t++) {
            const ulonglong2* tp = reinterpret_cast<const ulonglong2*>(sT + t * F4_PER_TRI);
            float2 r0 = tri_pair(tp, px2[0], py2[0], pz2[0], NEG1);
            float2 r1 = tri_pair(tp, px2[1], py2[1], pz2[1], NEG1);
            dm[0] = fminf(dm[0], r0.x);
            dm[1] = fminf(dm[1], r0.y);
            dm[2] = fminf(dm[2], r1.x);
            dm[3] = fminf(dm[3], r1.y);
        }
    }
#pragma unroll
    for (int k = 0; k < PPT; k++)
        atomicMin(&g_dmin[b * NP + ibase + k * TPB], __float_as_uint(dm[k]));
}

// Kernel 4a: parallel partial reduce. 32 blocks (8 slices x 4 batches) x 512 thr.
__global__ void reduceA_kernel(const float* __restrict__ pc) {
    __shared__ float sd[512];
    __shared__ float sc[512];
    int tid = threadIdx.x;
    int blk = blockIdx.x;
    int b = blk >> 3;
    int slice = blk & 7;
    int i = slice * 512 + tid;
    const float* p = pc + ((size_t)b * NP + i) * 3;
    float x = p[0], y = p[1], z = p[2];
    float m = (x != 0.0f || y != 0.0f || z != 0.0f) ? 1.0f : 0.0f;
    sd[tid] = __uint_as_float(g_dmin[b * NP + i]) * m;
    sc[tid] = m;
    __syncthreads();
    for (int s = 256; s > 0; s >>= 1) {
        if (tid < s) {
            sd[tid] += sd[tid + s];
            sc[tid] += sc[tid + s];
        }
        __syncthreads();
    }
    if (tid == 0) {
        g_psum[blk] = sd[0];
        g_pcnt[blk] = sc[0];
    }
}

// Kernel 4b: deterministic fixed-order final combine.
__global__ void reduceB_kernel(float* __restrict__ out) {
    if (threadIdx.x == 0) {
        float acc = 0.0f;
        for (int b = 0; b < NB; b++) {
            float s = 0.0f, c = 0.0f;
#pragma unroll
            for (int j = 0; j < 8; j++) {
                s += g_psum[b * 8 + j];
                c += g_pcnt[b * 8 + j];
            }
            acc += s / fmaxf(c, 1.0f);
        }
        out[0] = acc * (1.0f / NB);
    }
}

extern "C" void kernel_launch(void* const* d_in, const int* in_sizes, int n_in,
                              void* d_out, int out_size) {
    const float* vertices = (const float*)d_in[0];
    const float* pc = (const float*)d_in[1];
    const int* faces = (const int*)d_in[2];
    float* out = (float*)d_out;

    prep_kernel<<<(NB * 3 * NV + 255) / 256, 256>>>(vertices);
    tri_kernel<<<(NB * NT + 255) / 256, 256>>>(faces);
    dist_kernel<<<dim3(CHUNKS, NP / (PPT * TPB), NB), TPB>>>(pc);
    reduceA_kernel<<<32, 512>>>(pc);
    reduceB_kernel<<<1, 32>>>(out);
}